// round 8
// baseline (speedup 1.0000x reference)
#include <cuda_runtime.h>

#define NB 64
#define NM 80
#define NT 4000
#define NCH 50        // chunks per row
#define LCH 80        // chunk length = NT/NCH, multiple of 4
#define ROWS (NB * NM)            // 5120
#define NSUM (NCH * ROWS)         // 256000
#define GATE_BLOCKS 500           // 500*128 = 64000 gate threads
#define SUM_BLOCKS  2000          // 2000*128 = 256000 summary threads

__device__ float g_gate[NB * NT];
__device__ float g_Bn[NSUM];      // chunk affine offsets (ns filter)
__device__ float g_Bs[NSUM];      // chunk affine offsets (st filter)
__device__ float g_Sn[NSUM];      // exact seed state entering each chunk (ns)
__device__ float g_Ss[NSUM];      // exact seed state entering each chunk (st)

__device__ __forceinline__ float clampf(float x, float lo, float hi) {
    return fminf(fmaxf(x, lo), hi);
}
__device__ __forceinline__ float sigmoidf(float x) {
    return 1.0f / (1.0f + __expf(-x));
}

// ---------------------------------------------------------------------------
// Kernel 1 (fused): block-role split.
//   blocks [0, GATE_BLOCKS): spectral-flatness gate per (b, 4t)
//   blocks [GATE_BLOCKS, +SUM_BLOCKS): per-(row,chunk) affine summary B
// ---------------------------------------------------------------------------
__global__ void __launch_bounds__(128) k1_gate_sum(
    const float* __restrict__ mel,
    const float* __restrict__ gate_temp,
    const float* __restrict__ ls_ns, const float* __restrict__ ls_st)
{
    if (blockIdx.x < GATE_BLOCKS) {
        // ---------------- gate role ----------------
        int idx = blockIdx.x * 128 + threadIdx.x;   // < 64000 exactly
        int b  = idx / (NT / 4);
        int t4 = idx - b * (NT / 4);

        const float4* base = reinterpret_cast<const float4*>(mel)
                             + (size_t)b * NM * (NT / 4) + t4;

        float sum[4]  = {0.f, 0.f, 0.f, 0.f};
        float low[4]  = {0.f, 0.f, 0.f, 0.f};
        float high[4] = {0.f, 0.f, 0.f, 0.f};
        float lp[4]   = {0.f, 0.f, 0.f, 0.f};

        #pragma unroll
        for (int g = 0; g < 4; ++g) {
            float p[4] = {1.f, 1.f, 1.f, 1.f};
            #pragma unroll
            for (int j = 0; j < 20; ++j) {
                const int m = g * 20 + j;
                float4 v = base[(size_t)m * (NT / 4)];
                float xv[4] = {v.x, v.y, v.z, v.w};
                #pragma unroll
                for (int k = 0; k < 4; ++k) {
                    sum[k] += xv[k];
                    p[k]   *= xv[k] + 1e-8f;
                    if (m < 26)  low[k]  += xv[k];   // M//3 = 26
                    if (m >= 53) high[k] += xv[k];   // 2*M//3 = 53
                }
            }
            #pragma unroll
            for (int k = 0; k < 4; ++k) lp[k] += __log2f(p[k]);
        }

        const float gt = gate_temp[0];
        float4 gout;
        float* go = &gout.x;
        #pragma unroll
        for (int k = 0; k < 4; ++k) {
            float arith = sum[k] * (1.0f / NM) + 1e-8f;
            float geo   = exp2f(lp[k] * (1.0f / NM));
            float sf    = clampf(__fdividef(geo, arith), 0.f, 1.f);
            float lo_   = low[k]  * (1.0f / 26.0f);
            float hi_   = high[k] * (1.0f / 27.0f);
            float tilt  = clampf(__fdividef(lo_, lo_ + hi_ + 1e-8f), 0.f, 1.f);
            float sfa   = sf + (1.0f - sf) * fmaxf(tilt - 0.6f, 0.f);
            go[k] = sigmoidf(gt * (sfa - 0.5f));
        }
        reinterpret_cast<float4*>(g_gate)[idx] = gout;
    } else {
        // ---------------- summary role ----------------
        int tid = (blockIdx.x - GATE_BLOCKS) * 128 + threadIdx.x;  // < 256000
        int chunk = tid / ROWS;
        int row   = tid - chunk * ROWS;
        int m = row % NM;

        const float s_ns = clampf(sigmoidf(ls_ns[m]), 0.05f, 0.3f);
        const float a_ns = 1.0f - s_ns;
        const float s_st = clampf(sigmoidf(ls_st[m]), 0.05f, 0.3f);
        const float a_st = 1.0f - s_st;

        const float a2n = a_ns * a_ns, a4n = a2n * a2n;
        const float a2s = a_st * a_st, a4s = a2s * a2s;
        const float sa1n = s_ns * a_ns, sa2n = s_ns * a2n, sa3n = sa2n * a_ns;
        const float sa1s = s_st * a_st, sa2s = s_st * a2s, sa3s = sa2s * a_st;

        const float* x = mel + (size_t)row * NT + chunk * LCH;

        float Bn = 0.f, Bs = 0.f;
        #pragma unroll 4
        for (int i = 0; i < LCH; i += 4) {
            float4 v = *reinterpret_cast<const float4*>(x + i);
            float pn = fmaf(sa3n, v.x, fmaf(sa2n, v.y, fmaf(sa1n, v.z, s_ns * v.w)));
            float ps = fmaf(sa3s, v.x, fmaf(sa2s, v.y, fmaf(sa1s, v.z, s_st * v.w)));
            Bn = fmaf(a4n, Bn, pn);
            Bs = fmaf(a4s, Bs, ps);
        }
        g_Bn[tid] = Bn;
        g_Bs[tid] = Bs;
    }
}

// ---------------------------------------------------------------------------
// Kernel 2: per-row serial scan over the 50 chunk summaries -> exact seeds.
// Thread r handles row r. Loads/stores at k*ROWS+r are fully coalesced.
// ---------------------------------------------------------------------------
__global__ void __launch_bounds__(256) k2_scan(
    const float* __restrict__ mel,
    const float* __restrict__ ls_ns, const float* __restrict__ ls_st)
{
    int r = blockIdx.x * 256 + threadIdx.x;
    if (r >= ROWS) return;
    int m = r % NM;

    const float s_ns = clampf(sigmoidf(ls_ns[m]), 0.05f, 0.3f);
    const float a_ns = 1.0f - s_ns;
    const float s_st = clampf(sigmoidf(ls_st[m]), 0.05f, 0.3f);
    const float a_st = 1.0f - s_st;

    // A = a^LCH (LCH = 80 = 64 + 16)
    float a2n = a_ns * a_ns, a4n = a2n * a2n, a8n = a4n * a4n, a16n = a8n * a8n;
    float a32n = a16n * a16n, a64n = a32n * a32n;
    const float An = a64n * a16n;
    float a2s = a_st * a_st, a4s = a2s * a2s, a8s = a4s * a4s, a16s = a8s * a8s;
    float a32s = a16s * a16s, a64s = a32s * a32s;
    const float As = a64s * a16s;

    float Sn = mel[(size_t)r * NT];   // S_{-1} = x_0
    float Ss = Sn;

    #pragma unroll
    for (int k = 0; k < NCH; ++k) {
        int idx = k * ROWS + r;
        g_Sn[idx] = Sn;
        g_Ss[idx] = Ss;
        Sn = fmaf(An, Sn, g_Bn[idx]);
        Ss = fmaf(As, Ss, g_Bs[idx]);
    }
}

// ---------------------------------------------------------------------------
// Kernel 3: main PCEN. Thread per (row, chunk) with exact seed; 80 outputs.
// Closed-form 4x unroll: carried dependency is 1 FMA per 4 samples.
// ---------------------------------------------------------------------------
__global__ void __launch_bounds__(256, 6) k3_pcen(
    const float* __restrict__ mel,
    const float* __restrict__ ls_ns, const float* __restrict__ la_ns,
    const float* __restrict__ ld_ns, const float* __restrict__ lr_ns,
    const float* __restrict__ ls_st, const float* __restrict__ la_st,
    const float* __restrict__ ld_st, const float* __restrict__ lr_st,
    float* __restrict__ out)
{
    int tid = blockIdx.x * 256 + threadIdx.x;
    if (tid >= NSUM) return;
    int chunk = tid / ROWS;
    int row   = tid - chunk * ROWS;
    int b = row / NM;
    int m = row - b * NM;

    const float s_ns  = clampf(sigmoidf(ls_ns[m]), 0.05f, 0.3f);
    const float a_ns  = 1.0f - s_ns;
    const float a2n = a_ns * a_ns, a3n = a2n * a_ns, a4n = a2n * a2n;
    const float al_ns = clampf(sigmoidf(la_ns[m]), 0.9f, 0.999f);
    const float d_ns  = clampf(__expf(ld_ns[m]), 0.5f, 5.0f);
    const float r_ns  = clampf(sigmoidf(lr_ns[m]), 0.05f, 0.25f);
    const float dp_ns = __powf(d_ns, r_ns);

    const float s_st  = clampf(sigmoidf(ls_st[m]), 0.05f, 0.3f);
    const float a_st  = 1.0f - s_st;
    const float a2s = a_st * a_st, a3s = a2s * a_st, a4s = a2s * a2s;
    const float al_st = clampf(sigmoidf(la_st[m]), 0.9f, 0.999f);
    const float d_st  = clampf(__expf(ld_st[m]), 0.001f, 0.1f);
    const float r_st  = clampf(sigmoidf(lr_st[m]), 0.05f, 0.25f);
    const float dp_st = __powf(d_st, r_st);

    const float* x  = mel + (size_t)row * NT + chunk * LCH;
    const float* gp = g_gate + (size_t)b * NT + chunk * LCH;
    float* o        = out + (size_t)row * NT + chunk * LCH;

    float sm_ns = g_Sn[tid];
    float sm_st = g_Ss[tid];

#define PCEN_OUT(smn, sms, xx, gg, oo) do {                            \
        float gn = __powf(1e-6f + (smn), -al_ns);                      \
        float on = __powf(fmaf((xx), gn, d_ns), r_ns) - dp_ns;         \
        float gs = __powf(1e-6f + (sms), -al_st);                      \
        float os = __powf(fmaf((xx), gs, d_st), r_st) - dp_st;         \
        (oo) = fmaf((gg), os - on, on);                                \
    } while (0)

    #pragma unroll 5
    for (int t = 0; t < LCH; t += 4) {
        float4 v = *reinterpret_cast<const float4*>(x + t);
        float4 g = *reinterpret_cast<const float4*>(gp + t);

        // prefix combos (independent of carried state)
        float u1n = fmaf(a_ns, v.x, v.y);
        float u2n = fmaf(a_ns, u1n, v.z);
        float u3n = fmaf(a_ns, u2n, v.w);
        float u1s = fmaf(a_st, v.x, v.y);
        float u2s = fmaf(a_st, u1s, v.z);
        float u3s = fmaf(a_st, u2s, v.w);

        float n1 = fmaf(a_ns, sm_ns, s_ns * v.x);
        float n2 = fmaf(a2n,  sm_ns, s_ns * u1n);
        float n3 = fmaf(a3n,  sm_ns, s_ns * u2n);
        float n4 = fmaf(a4n,  sm_ns, s_ns * u3n);
        float s1 = fmaf(a_st, sm_st, s_st * v.x);
        float s2 = fmaf(a2s,  sm_st, s_st * u1s);
        float s3 = fmaf(a3s,  sm_st, s_st * u2s);
        float s4 = fmaf(a4s,  sm_st, s_st * u3s);
        sm_ns = n4;
        sm_st = s4;

        float4 ov;
        PCEN_OUT(n1, s1, v.x, g.x, ov.x);
        PCEN_OUT(n2, s2, v.y, g.y, ov.y);
        PCEN_OUT(n3, s3, v.z, g.z, ov.z);
        PCEN_OUT(n4, s4, v.w, g.w, ov.w);
        *reinterpret_cast<float4*>(o + t) = ov;
    }
#undef PCEN_OUT
}

extern "C" void kernel_launch(void* const* d_in, const int* in_sizes, int n_in,
                              void* d_out, int out_size)
{
    const float* mel = (const float*)d_in[0];
    const float* ls_ns = (const float*)d_in[1];
    const float* la_ns = (const float*)d_in[2];
    const float* ld_ns = (const float*)d_in[3];
    const float* lr_ns = (const float*)d_in[4];
    const float* ls_st = (const float*)d_in[5];
    const float* la_st = (const float*)d_in[6];
    const float* ld_st = (const float*)d_in[7];
    const float* lr_st = (const float*)d_in[8];
    const float* gate_temp = (const float*)d_in[9];
    float* out = (float*)d_out;

    k1_gate_sum<<<GATE_BLOCKS + SUM_BLOCKS, 128>>>(mel, gate_temp, ls_ns, ls_st);
    k2_scan<<<(ROWS + 255) / 256, 256>>>(mel, ls_ns, ls_st);
    k3_pcen<<<(NSUM + 255) / 256, 256>>>(
        mel, ls_ns, la_ns, ld_ns, lr_ns, ls_st, la_st, ld_st, lr_st, out);
}

// round 9
// speedup vs baseline: 1.4686x; 1.4686x over previous
#include <cuda_runtime.h>

#define NB 64
#define NM 80
#define NT 4000
#define NCH 50        // chunks per row
#define LCH 80        // chunk length = NT/NCH, multiple of 4
#define HCH 25        // NCH/2: chunk-pair offset
#define ROWS (NB * NM)            // 5120
#define NSUM (NCH * ROWS)         // 256000
#define GATE_BLOCKS 500           // 500*128 = 64000 gate threads
#define SUM_BLOCKS  2000          // 2000*128 = 256000 summary threads

__device__ float g_gate[NB * NT];
__device__ float g_Bn[NSUM];      // chunk affine offsets (ns filter)
__device__ float g_Bs[NSUM];      // chunk affine offsets (st filter)
__device__ float g_Sn[NSUM];      // exact seed state entering each chunk (ns)
__device__ float g_Ss[NSUM];      // exact seed state entering each chunk (st)

__device__ __forceinline__ float clampf(float x, float lo, float hi) {
    return fminf(fmaxf(x, lo), hi);
}
__device__ __forceinline__ float sigmoidf(float x) {
    return 1.0f / (1.0f + __expf(-x));
}

// ---------------------------------------------------------------------------
// Kernel 1 (fused): block-role split.
//   blocks [0, GATE_BLOCKS): spectral-flatness gate per (b, 4t)
//   blocks [GATE_BLOCKS, +SUM_BLOCKS): per-(row,chunk) affine summary B
// ---------------------------------------------------------------------------
__global__ void __launch_bounds__(128) k1_gate_sum(
    const float* __restrict__ mel,
    const float* __restrict__ gate_temp,
    const float* __restrict__ ls_ns, const float* __restrict__ ls_st)
{
    if (blockIdx.x < GATE_BLOCKS) {
        // ---------------- gate role ----------------
        int idx = blockIdx.x * 128 + threadIdx.x;   // < 64000 exactly
        int b  = idx / (NT / 4);
        int t4 = idx - b * (NT / 4);

        const float4* base = reinterpret_cast<const float4*>(mel)
                             + (size_t)b * NM * (NT / 4) + t4;

        float sum[4]  = {0.f, 0.f, 0.f, 0.f};
        float low[4]  = {0.f, 0.f, 0.f, 0.f};
        float high[4] = {0.f, 0.f, 0.f, 0.f};
        float lp[4]   = {0.f, 0.f, 0.f, 0.f};

        #pragma unroll
        for (int g = 0; g < 4; ++g) {
            float p[4] = {1.f, 1.f, 1.f, 1.f};
            #pragma unroll
            for (int j = 0; j < 20; ++j) {
                const int m = g * 20 + j;
                float4 v = base[(size_t)m * (NT / 4)];
                float xv[4] = {v.x, v.y, v.z, v.w};
                #pragma unroll
                for (int k = 0; k < 4; ++k) {
                    sum[k] += xv[k];
                    p[k]   *= xv[k] + 1e-8f;
                    if (m < 26)  low[k]  += xv[k];   // M//3 = 26
                    if (m >= 53) high[k] += xv[k];   // 2*M//3 = 53
                }
            }
            #pragma unroll
            for (int k = 0; k < 4; ++k) lp[k] += __log2f(p[k]);
        }

        const float gt = gate_temp[0];
        float4 gout;
        float* go = &gout.x;
        #pragma unroll
        for (int k = 0; k < 4; ++k) {
            float arith = sum[k] * (1.0f / NM) + 1e-8f;
            float geo   = exp2f(lp[k] * (1.0f / NM));
            float sf    = clampf(__fdividef(geo, arith), 0.f, 1.f);
            float lo_   = low[k]  * (1.0f / 26.0f);
            float hi_   = high[k] * (1.0f / 27.0f);
            float tilt  = clampf(__fdividef(lo_, lo_ + hi_ + 1e-8f), 0.f, 1.f);
            float sfa   = sf + (1.0f - sf) * fmaxf(tilt - 0.6f, 0.f);
            go[k] = sigmoidf(gt * (sfa - 0.5f));
        }
        reinterpret_cast<float4*>(g_gate)[idx] = gout;
    } else {
        // ---------------- summary role ----------------
        int tid = (blockIdx.x - GATE_BLOCKS) * 128 + threadIdx.x;  // < 256000
        int chunk = tid / ROWS;
        int row   = tid - chunk * ROWS;
        int m = row % NM;

        const float s_ns = clampf(sigmoidf(ls_ns[m]), 0.05f, 0.3f);
        const float a_ns = 1.0f - s_ns;
        const float s_st = clampf(sigmoidf(ls_st[m]), 0.05f, 0.3f);
        const float a_st = 1.0f - s_st;

        const float a2n = a_ns * a_ns, a4n = a2n * a2n;
        const float a2s = a_st * a_st, a4s = a2s * a2s;
        const float sa1n = s_ns * a_ns, sa2n = s_ns * a2n, sa3n = sa2n * a_ns;
        const float sa1s = s_st * a_st, sa2s = s_st * a2s, sa3s = sa2s * a_st;

        const float* x = mel + (size_t)row * NT + chunk * LCH;

        float Bn = 0.f, Bs = 0.f;
        #pragma unroll 4
        for (int i = 0; i < LCH; i += 4) {
            float4 v = *reinterpret_cast<const float4*>(x + i);
            float pn = fmaf(sa3n, v.x, fmaf(sa2n, v.y, fmaf(sa1n, v.z, s_ns * v.w)));
            float ps = fmaf(sa3s, v.x, fmaf(sa2s, v.y, fmaf(sa1s, v.z, s_st * v.w)));
            Bn = fmaf(a4n, Bn, pn);
            Bs = fmaf(a4s, Bs, ps);
        }
        g_Bn[tid] = Bn;
        g_Bs[tid] = Bs;
    }
}

// ---------------------------------------------------------------------------
// Kernel 2: per-row serial scan over the 50 chunk summaries -> exact seeds.
// ---------------------------------------------------------------------------
__global__ void __launch_bounds__(256) k2_scan(
    const float* __restrict__ mel,
    const float* __restrict__ ls_ns, const float* __restrict__ ls_st)
{
    int r = blockIdx.x * 256 + threadIdx.x;
    if (r >= ROWS) return;
    int m = r % NM;

    const float s_ns = clampf(sigmoidf(ls_ns[m]), 0.05f, 0.3f);
    const float a_ns = 1.0f - s_ns;
    const float s_st = clampf(sigmoidf(ls_st[m]), 0.05f, 0.3f);
    const float a_st = 1.0f - s_st;

    // A = a^LCH (LCH = 80 = 64 + 16)
    float a2n = a_ns * a_ns, a4n = a2n * a2n, a8n = a4n * a4n, a16n = a8n * a8n;
    float a32n = a16n * a16n, a64n = a32n * a32n;
    const float An = a64n * a16n;
    float a2s = a_st * a_st, a4s = a2s * a2s, a8s = a4s * a4s, a16s = a8s * a8s;
    float a32s = a16s * a16s, a64s = a32s * a32s;
    const float As = a64s * a16s;

    float Sn = mel[(size_t)r * NT];   // S_{-1} = x_0
    float Ss = Sn;

    #pragma unroll
    for (int k = 0; k < NCH; ++k) {
        int idx = k * ROWS + r;
        g_Sn[idx] = Sn;
        g_Ss[idx] = Ss;
        Sn = fmaf(An, Sn, g_Bn[idx]);
        Ss = fmaf(As, Ss, g_Bs[idx]);
    }
}

// ---------------------------------------------------------------------------
// Kernel 3: main PCEN, dual-stream. Thread owns chunks c and c+25 of one row
// (shared filter params, independent IIR chains -> 2x ILP on MUFU paths).
// 1000 blocks x 128 thr, 7 resident/SM -> single wave.
// ---------------------------------------------------------------------------
__global__ void __launch_bounds__(128, 7) k3_pcen(
    const float* __restrict__ mel,
    const float* __restrict__ ls_ns, const float* __restrict__ la_ns,
    const float* __restrict__ ld_ns, const float* __restrict__ lr_ns,
    const float* __restrict__ ls_st, const float* __restrict__ la_st,
    const float* __restrict__ ld_st, const float* __restrict__ lr_st,
    float* __restrict__ out)
{
    int tid = blockIdx.x * 128 + threadIdx.x;   // < 128000 exactly
    int c0  = tid / ROWS;                        // 0..24
    int row = tid - c0 * ROWS;
    int b = row / NM;
    int m = row - b * NM;

    const float s_ns  = clampf(sigmoidf(ls_ns[m]), 0.05f, 0.3f);
    const float a_ns  = 1.0f - s_ns;
    const float a2n = a_ns * a_ns, a3n = a2n * a_ns, a4n = a2n * a2n;
    const float al_ns = clampf(sigmoidf(la_ns[m]), 0.9f, 0.999f);
    const float d_ns  = clampf(__expf(ld_ns[m]), 0.5f, 5.0f);
    const float r_ns  = clampf(sigmoidf(lr_ns[m]), 0.05f, 0.25f);
    const float dp_ns = __powf(d_ns, r_ns);

    const float s_st  = clampf(sigmoidf(ls_st[m]), 0.05f, 0.3f);
    const float a_st  = 1.0f - s_st;
    const float a2s = a_st * a_st, a3s = a2s * a_st, a4s = a2s * a2s;
    const float al_st = clampf(sigmoidf(la_st[m]), 0.9f, 0.999f);
    const float d_st  = clampf(__expf(ld_st[m]), 0.001f, 0.1f);
    const float r_st  = clampf(sigmoidf(lr_st[m]), 0.05f, 0.25f);
    const float dp_st = __powf(d_st, r_st);

    const float* x0 = mel + (size_t)row * NT + c0 * LCH;
    const float* x1 = x0 + HCH * LCH;
    const float* q0 = g_gate + (size_t)b * NT + c0 * LCH;
    const float* q1 = q0 + HCH * LCH;
    float* o0 = out + (size_t)row * NT + c0 * LCH;
    float* o1 = o0 + HCH * LCH;

    float smn0 = g_Sn[c0 * ROWS + row];
    float sms0 = g_Ss[c0 * ROWS + row];
    float smn1 = g_Sn[(c0 + HCH) * ROWS + row];
    float sms1 = g_Ss[(c0 + HCH) * ROWS + row];

#define PCEN_OUT(smn, sms, xx, gg, oo) do {                            \
        float gn = __powf(1e-6f + (smn), -al_ns);                      \
        float on = __powf(fmaf((xx), gn, d_ns), r_ns) - dp_ns;         \
        float gs = __powf(1e-6f + (sms), -al_st);                      \
        float os = __powf(fmaf((xx), gs, d_st), r_st) - dp_st;         \
        (oo) = fmaf((gg), os - on, on);                                \
    } while (0)

#define STEP4(vv, smn, sms, gg, oo) do {                               \
        float u1n = fmaf(a_ns, (vv).x, (vv).y);                        \
        float u2n = fmaf(a_ns, u1n, (vv).z);                           \
        float u3n = fmaf(a_ns, u2n, (vv).w);                           \
        float u1s = fmaf(a_st, (vv).x, (vv).y);                        \
        float u2s = fmaf(a_st, u1s, (vv).z);                           \
        float u3s = fmaf(a_st, u2s, (vv).w);                           \
        float n1 = fmaf(a_ns, (smn), s_ns * (vv).x);                   \
        float n2 = fmaf(a2n,  (smn), s_ns * u1n);                      \
        float n3 = fmaf(a3n,  (smn), s_ns * u2n);                      \
        float n4 = fmaf(a4n,  (smn), s_ns * u3n);                      \
        float t1 = fmaf(a_st, (sms), s_st * (vv).x);                   \
        float t2 = fmaf(a2s,  (sms), s_st * u1s);                      \
        float t3 = fmaf(a3s,  (sms), s_st * u2s);                      \
        float t4 = fmaf(a4s,  (sms), s_st * u3s);                      \
        (smn) = n4; (sms) = t4;                                        \
        PCEN_OUT(n1, t1, (vv).x, (gg).x, (oo).x);                      \
        PCEN_OUT(n2, t2, (vv).y, (gg).y, (oo).y);                      \
        PCEN_OUT(n3, t3, (vv).z, (gg).z, (oo).z);                      \
        PCEN_OUT(n4, t4, (vv).w, (gg).w, (oo).w);                      \
    } while (0)

    #pragma unroll 2
    for (int t = 0; t < LCH; t += 4) {
        float4 v0 = *reinterpret_cast<const float4*>(x0 + t);
        float4 g0 = *reinterpret_cast<const float4*>(q0 + t);
        float4 v1 = *reinterpret_cast<const float4*>(x1 + t);
        float4 g1 = *reinterpret_cast<const float4*>(q1 + t);
        float4 ov0, ov1;
        STEP4(v0, smn0, sms0, g0, ov0);
        STEP4(v1, smn1, sms1, g1, ov1);
        *reinterpret_cast<float4*>(o0 + t) = ov0;
        *reinterpret_cast<float4*>(o1 + t) = ov1;
    }
#undef STEP4
#undef PCEN_OUT
}

extern "C" void kernel_launch(void* const* d_in, const int* in_sizes, int n_in,
                              void* d_out, int out_size)
{
    const float* mel = (const float*)d_in[0];
    const float* ls_ns = (const float*)d_in[1];
    const float* la_ns = (const float*)d_in[2];
    const float* ld_ns = (const float*)d_in[3];
    const float* lr_ns = (const float*)d_in[4];
    const float* ls_st = (const float*)d_in[5];
    const float* la_st = (const float*)d_in[6];
    const float* ld_st = (const float*)d_in[7];
    const float* lr_st = (const float*)d_in[8];
    const float* gate_temp = (const float*)d_in[9];
    float* out = (float*)d_out;

    k1_gate_sum<<<GATE_BLOCKS + SUM_BLOCKS, 128>>>(mel, gate_temp, ls_ns, ls_st);
    k2_scan<<<(ROWS + 255) / 256, 256>>>(mel, ls_ns, ls_st);
    k3_pcen<<<(NSUM / 2) / 128, 128>>>(
        mel, ls_ns, la_ns, ld_ns, lr_ns, ls_st, la_st, ld_st, lr_st, out);
}